// round 9
// baseline (speedup 1.0000x reference)
#include <cuda_runtime.h>
#include <cstdint>

#define DIM   1024
#define HEADS 16
#define HD    64
#define BATCH 2
#define SEQ   2048
#define MROWS (BATCH*SEQ)      /* 4096 */
#define ATT_SCALE 0.125f       /* 64^-0.5 */

// -------- scratch (device globals: allocation-free) --------
__device__ float g_Q[HEADS*BATCH*SEQ*HD];   // [bh][n][d]
__device__ float g_K[HEADS*BATCH*SEQ*HD];
__device__ float g_V[HEADS*BATCH*SEQ*HD];
__device__ float g_C[MROWS*DIM];            // [b*SEQ+n][h*HD+d]

// -------- packed f32x2 helpers (2x fp32 throughput on sm_103a) --------
__device__ __forceinline__ unsigned long long pack2(float lo, float hi) {
    unsigned long long r;
    asm("mov.b64 %0, {%1, %2};" : "=l"(r) : "f"(lo), "f"(hi));
    return r;
}
__device__ __forceinline__ void unpack2(unsigned long long v, float& lo, float& hi) {
    asm("mov.b64 {%0, %1}, %2;" : "=f"(lo), "=f"(hi) : "l"(v));
}
__device__ __forceinline__ void ffma2(unsigned long long& d, unsigned long long a, unsigned long long b) {
    asm("fma.rn.f32x2 %0, %1, %2, %0;" : "+l"(d) : "l"(a), "l"(b));
}
__device__ __forceinline__ void fmul2(unsigned long long& d, unsigned long long a) {
    asm("mul.rn.f32x2 %0, %0, %1;" : "+l"(d) : "l"(a));
}

// ============================================================
// GEMM: out = A @ W^T + bias.  A:[4096,1024] W:[1024,1024] row-major.
// permute=1: write out[m, j] -> g_X[((b*16+h)*SEQ + n)*HD + d]  (b,h,n,d)
// permute=0: write out[m*DIM + j]
// Tiles: BM=BN=128, BK=8, 256 threads, 8x8 micro-tile, f32x2 packed.
// Double-buffered smem: LDG for tile t+1 issued before compute of tile t,
// STS into the other buffer after compute, ONE barrier per k-tile.
// Global loads: row = tid>>1, khalf = (tid&1)*4  ->  each warp covers
// 16 rows x 32 contiguous bytes = 100% sector utilization.
// ============================================================
__global__ __launch_bounds__(256, 2)
void gemm_kernel(const float* __restrict__ A, const float* __restrict__ W,
                 const float* __restrict__ bias, float* __restrict__ out,
                 int permute)
{
    __shared__ float As[2][8][128];
    __shared__ float Bs[2][8][128];

    const int tid = threadIdx.x;
    const int m0  = blockIdx.y * 128;
    const int n0  = blockIdx.x * 128;
    const int ty  = tid >> 4;      // 0..15
    const int tx  = tid & 15;      // 0..15

    const int lrow = tid >> 1;         // tile row for loads (coalesced LDG)
    const int lk4  = (tid & 1) * 4;    // k offset: 0 or 4

    unsigned long long acc[8][4];
#pragma unroll
    for (int i = 0; i < 8; ++i)
#pragma unroll
        for (int j = 0; j < 4; ++j) acc[i][j] = 0ULL;

    const float* Ap = A + (size_t)(m0 + lrow) * DIM + lk4;
    const float* Wp = W + (size_t)(n0 + lrow) * DIM + lk4;

    // preload k-tile 0 into buffer 0
    {
        float4 av = *(const float4*)(Ap);
        float4 bv = *(const float4*)(Wp);
        As[0][lk4+0][lrow] = av.x; As[0][lk4+1][lrow] = av.y;
        As[0][lk4+2][lrow] = av.z; As[0][lk4+3][lrow] = av.w;
        Bs[0][lk4+0][lrow] = bv.x; Bs[0][lk4+1][lrow] = bv.y;
        Bs[0][lk4+2][lrow] = bv.z; Bs[0][lk4+3][lrow] = bv.w;
    }
    __syncthreads();

    for (int kt = 0; kt < DIM; kt += 8) {
        const int buf = (kt >> 3) & 1;
        const bool has_next = (kt + 8) < DIM;

        // issue next tile's global loads early (latency hidden by compute)
        float4 av2, bv2;
        if (has_next) {
            av2 = *(const float4*)(Ap + kt + 8);
            bv2 = *(const float4*)(Wp + kt + 8);
        }

#pragma unroll
        for (int kk = 0; kk < 8; ++kk) {
            float4 a0 = *(const float4*)&As[buf][kk][ty*8];
            float4 a1 = *(const float4*)&As[buf][kk][ty*8+4];
            float4 b0 = *(const float4*)&Bs[buf][kk][tx*8];
            float4 b1 = *(const float4*)&Bs[buf][kk][tx*8+4];
            unsigned long long bb[4] = { pack2(b0.x,b0.y), pack2(b0.z,b0.w),
                                         pack2(b1.x,b1.y), pack2(b1.z,b1.w) };
            float ar[8] = { a0.x,a0.y,a0.z,a0.w, a1.x,a1.y,a1.z,a1.w };
#pragma unroll
            for (int i = 0; i < 8; ++i) {
                unsigned long long aa = pack2(ar[i], ar[i]);
#pragma unroll
                for (int j = 0; j < 4; ++j) ffma2(acc[i][j], aa, bb[j]);
            }
        }

        if (has_next) {
            const int nb = buf ^ 1;
            As[nb][lk4+0][lrow] = av2.x; As[nb][lk4+1][lrow] = av2.y;
            As[nb][lk4+2][lrow] = av2.z; As[nb][lk4+3][lrow] = av2.w;
            Bs[nb][lk4+0][lrow] = bv2.x; Bs[nb][lk4+1][lrow] = bv2.y;
            Bs[nb][lk4+2][lrow] = bv2.z; Bs[nb][lk4+3][lrow] = bv2.w;
        }
        __syncthreads();
    }

    // epilogue
#pragma unroll
    for (int i = 0; i < 8; ++i) {
        int m = m0 + ty*8 + i;
        int b = m >> 11;            // /SEQ
        int n = m & (SEQ - 1);
#pragma unroll
        for (int j = 0; j < 4; ++j) {
            float lo, hi; unpack2(acc[i][j], lo, hi);
            int c0 = n0 + tx*8 + j*2;
            lo += bias[c0]; hi += bias[c0+1];
            if (permute) {
                int h = c0 >> 6, d = c0 & 63;
                float* dst = out + ((size_t)(b*HEADS + h)*SEQ + n)*HD + d;
                dst[0] = lo; dst[1] = hi;   // same head (8 | 64)
            } else {
                float* dst = out + (size_t)m*DIM + c0;
                dst[0] = lo; dst[1] = hi;
            }
        }
    }
}

// ============================================================
// Flash attention (fp32, online softmax, SCALE applied post-softmax).
// Block: 256 threads = 16x16. One (bh, 128-query tile) per block.
// S stage:  rows = keys (8ty+i), cols = queries (8tx+j), f32x2 packed.
// O stage:  rows = queries (8ty+i), cols = d (4tx..), f32x2 packed.
// ============================================================
#define QT   (64*128)
#define KT   (64*128)
#define VSZ  (128*64)
#define PSZ  (128*128)
#define REDS (16*128)            /* 16 ty-groups x 128 queries */
#define ATT_SMEM_FLOATS (QT + KT + VSZ + PSZ + REDS + 3*128)
#define ATT_SMEM_BYTES  (ATT_SMEM_FLOATS * 4)

__global__ __launch_bounds__(256, 1)
void attn_kernel()
{
    extern __shared__ float sm[];
    float* Qt  = sm;                 // Qt[d*128 + q]
    float* Kt  = Qt + QT;            // Kt[d*128 + c]
    float* Vs  = Kt + KT;            // Vs[c*64 + d]
    float* Pt  = Vs + VSZ;           // Pt[c*128 + q]
    float* red = Pt + PSZ;           // red[t*128 + q], t = ty group 0..15
    float* m_arr  = red + REDS;      // [128]
    float* sc_arr = m_arr + 128;     // [128]
    float* l_arr  = sc_arr + 128;    // [128]

    const int tid = threadIdx.x;
    const int ty  = tid >> 4;
    const int tx  = tid & 15;
    const int bh  = blockIdx.y;
    const int q0  = blockIdx.x * 128;

    const float* Qg = g_Q + (size_t)bh * SEQ * HD;
    const float* Kg = g_K + (size_t)bh * SEQ * HD;
    const float* Vg = g_V + (size_t)bh * SEQ * HD;

    // load Q tile transposed: Qt[d][q]
#pragma unroll
    for (int it = 0; it < 8; ++it) {
        int idx = tid + it*256;             // 0..2047
        int qr  = idx & 127;
        int d4  = (idx >> 7) * 4;
        float4 v = *(const float4*)(Qg + (size_t)(q0 + qr)*HD + d4);
        Qt[(d4+0)*128 + qr] = v.x; Qt[(d4+1)*128 + qr] = v.y;
        Qt[(d4+2)*128 + qr] = v.z; Qt[(d4+3)*128 + qr] = v.w;
    }
    if (tid < 128) { m_arr[tid] = -1e30f; l_arr[tid] = 0.0f; }

    unsigned long long o2[8][2];
#pragma unroll
    for (int i = 0; i < 8; ++i) { o2[i][0] = 0ULL; o2[i][1] = 0ULL; }

    __syncthreads();

    for (int c0 = 0; c0 < SEQ; c0 += 128) {
        // ---- load K (transposed) + V tiles ----
#pragma unroll
        for (int it = 0; it < 8; ++it) {
            int idx = tid + it*256;
            int kr  = idx & 127;
            int d4  = (idx >> 7) * 4;
            float4 kv = *(const float4*)(Kg + (size_t)(c0 + kr)*HD + d4);
            Kt[(d4+0)*128 + kr] = kv.x; Kt[(d4+1)*128 + kr] = kv.y;
            Kt[(d4+2)*128 + kr] = kv.z; Kt[(d4+3)*128 + kr] = kv.w;
            float4 vv = *(const float4*)(Vg + (size_t)(c0 + kr)*HD + d4);
            *(float4*)(Vs + kr*64 + d4) = vv;
        }
        __syncthreads();   // (A)

        // ---- S = K . Q^T  (this thread: keys 8ty+i, query pairs) ----
        unsigned long long s2[8][4];
#pragma unroll
        for (int i = 0; i < 8; ++i)
#pragma unroll
            for (int j = 0; j < 4; ++j) s2[i][j] = 0ULL;

#pragma unroll 4
        for (int d = 0; d < HD; ++d) {
            const float* kd = Kt + d*128 + ty*8;
            const float* qd = Qt + d*128 + tx*8;
            float4 k0 = *(const float4*)kd;
            float4 k1 = *(const float4*)(kd + 4);
            float4 qa = *(const float4*)qd;
            float4 qb = *(const float4*)(qd + 4);
            unsigned long long qq[4] = { pack2(qa.x,qa.y), pack2(qa.z,qa.w),
                                         pack2(qb.x,qb.y), pack2(qb.z,qb.w) };
            float kr[8] = { k0.x,k0.y,k0.z,k0.w, k1.x,k1.y,k1.z,k1.w };
#pragma unroll
            for (int i = 0; i < 8; ++i) {
                unsigned long long aa = pack2(kr[i], kr[i]);
#pragma unroll
                for (int j = 0; j < 4; ++j) ffma2(s2[i][j], aa, qq[j]);
            }
        }

        // ---- column (per-query) max over this thread's 8 keys ----
        {
            float cmax[8];
#pragma unroll
            for (int j = 0; j < 8; ++j) cmax[j] = -1e30f;
#pragma unroll
            for (int i = 0; i < 8; ++i)
#pragma unroll
                for (int jp = 0; jp < 4; ++jp) {
                    float lo, hi; unpack2(s2[i][jp], lo, hi);
                    cmax[2*jp]   = fmaxf(cmax[2*jp], lo);
                    cmax[2*jp+1] = fmaxf(cmax[2*jp+1], hi);
                }
#pragma unroll
            for (int j = 0; j < 8; ++j) red[ty*128 + tx*8 + j] = cmax[j];
        }
        __syncthreads();   // (B)

        // ---- ty==0: finish max reduction over all 16 ty-groups ----
        if (ty == 0) {
#pragma unroll
            for (int j = 0; j < 8; ++j) {
                int q = tx*8 + j;
                float mx = red[q];
#pragma unroll
                for (int t = 1; t < 16; ++t) mx = fmaxf(mx, red[t*128 + q]);
                float mo = m_arr[q];
                float mn = fmaxf(mo, mx);
                m_arr[q]  = mn;
                sc_arr[q] = __expf(mo - mn);
            }
        }
        __syncthreads();   // (C)

        // ---- P = exp(S - m), store Pt[c][q], partial row sums ----
        {
            float mn[8];
#pragma unroll
            for (int j = 0; j < 8; ++j) mn[j] = m_arr[tx*8 + j];
            float psum[8];
#pragma unroll
            for (int j = 0; j < 8; ++j) psum[j] = 0.0f;
#pragma unroll
            for (int i = 0; i < 8; ++i) {
                float p[8];
#pragma unroll
                for (int jp = 0; jp < 4; ++jp) {
                    float lo, hi; unpack2(s2[i][jp], lo, hi);
                    p[2*jp]   = __expf(lo - mn[2*jp]);
                    p[2*jp+1] = __expf(hi - mn[2*jp+1]);
                }
#pragma unroll
                for (int j = 0; j < 8; ++j) psum[j] += p[j];
                float* pr = Pt + (ty*8 + i)*128 + tx*8;
                *(float4*)pr       = make_float4(p[0], p[1], p[2], p[3]);
                *(float4*)(pr + 4) = make_float4(p[4], p[5], p[6], p[7]);
            }
#pragma unroll
            for (int j = 0; j < 8; ++j) red[ty*128 + tx*8 + j] = psum[j];
        }
        __syncthreads();   // (D)

        // ---- ty==0: running denominator over all 16 ty-groups ----
        if (ty == 0) {
#pragma unroll
            for (int j = 0; j < 8; ++j) {
                int q = tx*8 + j;
                float s_ = 0.0f;
#pragma unroll
                for (int t = 0; t < 16; ++t) s_ += red[t*128 + q];
                l_arr[q] = l_arr[q] * sc_arr[q] + s_;
            }
        }

        // ---- O = sc*O + P @ V  (this thread: queries 8ty+i, d = 4tx..) ----
        {
            float scv;
#pragma unroll
            for (int i = 0; i < 8; ++i) {
                scv = sc_arr[ty*8 + i];
                unsigned long long ss = pack2(scv, scv);
                fmul2(o2[i][0], ss);
                fmul2(o2[i][1], ss);
            }
#pragma unroll 2
            for (int c = 0; c < 128; ++c) {
                const float* pr = Pt + c*128 + ty*8;
                float4 p0 = *(const float4*)pr;
                float4 p1 = *(const float4*)(pr + 4);
                float pv[8] = { p0.x,p0.y,p0.z,p0.w, p1.x,p1.y,p1.z,p1.w };
                float4 vv = *(const float4*)(Vs + c*64 + tx*4);
                unsigned long long v2[2] = { pack2(vv.x, vv.y), pack2(vv.z, vv.w) };
#pragma unroll
                for (int i = 0; i < 8; ++i) {
                    unsigned long long aa = pack2(pv[i], pv[i]);
                    ffma2(o2[i][0], aa, v2[0]);
                    ffma2(o2[i][1], aa, v2[1]);
                }
            }
        }
        __syncthreads();   // (E) — protects Kt/Vs/Pt/red for next tile
    }

    // ---- epilogue: out = O * SCALE / l, write to g_C [b,n,h*64+d] ----
    const int b = bh >> 4, h = bh & 15;
#pragma unroll
    for (int i = 0; i < 8; ++i) {
        int q = ty*8 + i;
        float inv = ATT_SCALE / l_arr[q];
        float o0, o1, o2_, o3;
        unpack2(o2[i][0], o0, o1);
        unpack2(o2[i][1], o2_, o3);
        float* dst = g_C + ((size_t)(b*SEQ + q0 + q) * HEADS + h) * HD + tx*4;
        *(float4*)dst = make_float4(o0*inv, o1*inv, o2_*inv, o3*inv);
    }
}

// ============================================================
extern "C" void kernel_launch(void* const* d_in, const int* in_sizes, int n_in,
                              void* d_out, int out_size)
{
    (void)in_sizes; (void)n_in; (void)out_size;
    const float* q  = (const float*)d_in[0];
    const float* k  = (const float*)d_in[1];
    const float* v  = (const float*)d_in[2];
    const float* Wq = (const float*)d_in[3];
    const float* bq = (const float*)d_in[4];
    const float* Wk = (const float*)d_in[5];
    const float* bk = (const float*)d_in[6];
    const float* Wv = (const float*)d_in[7];
    const float* bv = (const float*)d_in[8];
    const float* Wp = (const float*)d_in[9];
    const float* bp = (const float*)d_in[10];
    float* out = (float*)d_out;

    float *gq, *gk, *gv, *gc;
    cudaGetSymbolAddress((void**)&gq, g_Q);
    cudaGetSymbolAddress((void**)&gk, g_K);
    cudaGetSymbolAddress((void**)&gv, g_V);
    cudaGetSymbolAddress((void**)&gc, g_C);

    dim3 gb(DIM/128, MROWS/128);   // (8, 32)

    gemm_kernel<<<gb, 256>>>(q, Wq, bq, gq, 1);
    gemm_kernel<<<gb, 256>>>(k, Wk, bk, gk, 1);
    gemm_kernel<<<gb, 256>>>(v, Wv, bv, gv, 1);

    cudaFuncSetAttribute(attn_kernel,
                         cudaFuncAttributeMaxDynamicSharedMemorySize,
                         ATT_SMEM_BYTES);
    attn_kernel<<<dim3(SEQ/128, BATCH*HEADS), 256, ATT_SMEM_BYTES>>>();

    gemm_kernel<<<gb, 256>>>(gc, Wp, bp, out, 0);
}

// round 13
// speedup vs baseline: 2.1617x; 2.1617x over previous
#include <cuda_runtime.h>
#include <cuda_bf16.h>
#include <cstdint>

#define DIM   1024
#define HEADS 16
#define HD    64
#define BATCH 2
#define SEQ   2048
#define MROWS (BATCH*SEQ)      /* 4096 */
#define ATT_SCALE 0.125f       /* 64^-0.5 */

// -------- scratch (device globals: allocation-free) --------
__device__ float g_Q[HEADS*BATCH*SEQ*HD];   // [bh][n][d]
__device__ float g_K[HEADS*BATCH*SEQ*HD];
__device__ float g_V[HEADS*BATCH*SEQ*HD];
__device__ float g_C[MROWS*DIM];            // [b*SEQ+n][h*HD+d]

// -------- bf16 helpers --------
__device__ __forceinline__ unsigned short f2bfu(float x) {
    __nv_bfloat16 b = __float2bfloat16(x);
    return *reinterpret_cast<unsigned short*>(&b);
}
__device__ __forceinline__ float bfu2f(unsigned short u) {
    __nv_bfloat16 b = *reinterpret_cast<__nv_bfloat16*>(&u);
    return __bfloat162float(b);
}

__device__ __forceinline__ void mma16816(float* d, const unsigned* a, unsigned b0, unsigned b1) {
    asm volatile(
        "mma.sync.aligned.m16n8k16.row.col.f32.bf16.bf16.f32 "
        "{%0,%1,%2,%3}, {%4,%5,%6,%7}, {%8,%9}, {%0,%1,%2,%3};"
        : "+f"(d[0]), "+f"(d[1]), "+f"(d[2]), "+f"(d[3])
        : "r"(a[0]), "r"(a[1]), "r"(a[2]), "r"(a[3]), "r"(b0), "r"(b1));
}
__device__ __forceinline__ void ldmatrix_x4(unsigned* r, unsigned addr) {
    asm volatile(
        "ldmatrix.sync.aligned.m8n8.x4.shared.b16 {%0,%1,%2,%3}, [%4];"
        : "=r"(r[0]), "=r"(r[1]), "=r"(r[2]), "=r"(r[3]) : "r"(addr));
}

// ============================================================
// HMMA GEMM: out = A @ W^T + bias, bf16-split (hi+lo, 3 MMAs).
// (unchanged from round-10/11 audited version)
// ============================================================
#define GS_STRIDE 24
#define GS_ARR    (128*GS_STRIDE)
#define GS_BUF    (4*GS_ARR)
#define GEMM_SMEM_BYTES (2*GS_BUF*2)

__global__ __launch_bounds__(256)
void gemm_hmma(const float* __restrict__ A, const float* __restrict__ W,
               const float* __restrict__ bias, float* __restrict__ out,
               int permute)
{
    extern __shared__ unsigned short gsm[];

    const int tid  = threadIdx.x;
    const int wid  = tid >> 5, lane = tid & 31;
    const int wm   = wid & 3;
    const int wn   = wid >> 2;
    const int g    = lane >> 2;
    const int t2   = (lane & 3) * 2;
    const int lgrp = lane >> 3;
    const int lrow = lane & 7;

    const int m0 = blockIdx.y * 128;
    const int n0 = blockIdx.x * 128;

    const unsigned gsh = (unsigned)__cvta_generic_to_shared(gsm);

    float acc[2][8][4];
#pragma unroll
    for (int mt = 0; mt < 2; ++mt)
#pragma unroll
        for (int nt = 0; nt < 8; ++nt)
#pragma unroll
            for (int r = 0; r < 4; ++r) acc[mt][nt][r] = 0.0f;

    const int lrw = tid >> 1;
    const int c8  = (tid & 1) * 8;
    const float* Ap = A + (size_t)(m0 + lrw) * DIM + c8;
    const float* Wp = W + (size_t)(n0 + lrw) * DIM + c8;

    auto store_tile = [&](float4 a0, float4 a1, float4 w0, float4 w1, int buf) {
        unsigned short* Ah = gsm + buf*GS_BUF;
        unsigned short* Al = Ah + GS_ARR;
        unsigned short* Wh = Al + GS_ARR;
        unsigned short* Wl = Wh + GS_ARR;
        float xa[8] = { a0.x,a0.y,a0.z,a0.w, a1.x,a1.y,a1.z,a1.w };
        float xw[8] = { w0.x,w0.y,w0.z,w0.w, w1.x,w1.y,w1.z,w1.w };
        const int base = lrw * GS_STRIDE + c8;
#pragma unroll
        for (int j = 0; j < 4; ++j) {
            unsigned short ah0 = f2bfu(xa[2*j]),   ah1 = f2bfu(xa[2*j+1]);
            unsigned short al0 = f2bfu(xa[2*j]   - bfu2f(ah0));
            unsigned short al1 = f2bfu(xa[2*j+1] - bfu2f(ah1));
            unsigned short wh0 = f2bfu(xw[2*j]),   wh1 = f2bfu(xw[2*j+1]);
            unsigned short wl0 = f2bfu(xw[2*j]   - bfu2f(wh0));
            unsigned short wl1 = f2bfu(xw[2*j+1] - bfu2f(wh1));
            *(unsigned*)&Ah[base + 2*j] = (unsigned)ah0 | ((unsigned)ah1 << 16);
            *(unsigned*)&Al[base + 2*j] = (unsigned)al0 | ((unsigned)al1 << 16);
            *(unsigned*)&Wh[base + 2*j] = (unsigned)wh0 | ((unsigned)wh1 << 16);
            *(unsigned*)&Wl[base + 2*j] = (unsigned)wl0 | ((unsigned)wl1 << 16);
        }
    };

    {
        float4 a0 = *(const float4*)(Ap),     a1 = *(const float4*)(Ap + 4);
        float4 w0 = *(const float4*)(Wp),     w1 = *(const float4*)(Wp + 4);
        store_tile(a0, a1, w0, w1, 0);
    }
    __syncthreads();

    const unsigned aoff = (unsigned)(((wm*32 + (lgrp & 1)*8 + lrow) * GS_STRIDE
                                      + (lgrp >> 1)*8) * 2);
    const unsigned boff = (unsigned)(((wn*64 + (lgrp >> 1)*8 + lrow) * GS_STRIDE
                                      + (lgrp & 1)*8) * 2);

    for (int kt = 0; kt < DIM; kt += 16) {
        const int buf = (kt >> 4) & 1;
        const bool hn = (kt + 16) < DIM;

        float4 a0n, a1n, w0n, w1n;
        if (hn) {
            a0n = *(const float4*)(Ap + kt + 16);
            a1n = *(const float4*)(Ap + kt + 20);
            w0n = *(const float4*)(Wp + kt + 16);
            w1n = *(const float4*)(Wp + kt + 20);
        }

        const unsigned bufb = gsh + (unsigned)(buf * GS_BUF * 2);
        unsigned aH[2][4], aL[2][4];
#pragma unroll
        for (int mt = 0; mt < 2; ++mt) {
            unsigned ad = bufb + aoff + (unsigned)(mt * 16 * GS_STRIDE * 2);
            ldmatrix_x4(aH[mt], ad);
            ldmatrix_x4(aL[mt], ad + GS_ARR*2);
        }
        unsigned bH[4][4], bL[4][4];
#pragma unroll
        for (int p = 0; p < 4; ++p) {
            unsigned bd = bufb + (unsigned)(2*GS_ARR*2) + boff
                        + (unsigned)(p * 16 * GS_STRIDE * 2);
            ldmatrix_x4(bH[p], bd);
            ldmatrix_x4(bL[p], bd + GS_ARR*2);
        }

#pragma unroll
        for (int mt = 0; mt < 2; ++mt)
#pragma unroll
            for (int nt = 0; nt < 8; ++nt) {
                const int p = nt >> 1, o = (nt & 1) * 2;
                mma16816(acc[mt][nt], aH[mt], bH[p][o], bH[p][o+1]);
                mma16816(acc[mt][nt], aH[mt], bL[p][o], bL[p][o+1]);
                mma16816(acc[mt][nt], aL[mt], bH[p][o], bH[p][o+1]);
            }

        if (hn) store_tile(a0n, a1n, w0n, w1n, buf ^ 1);
        __syncthreads();
    }

#pragma unroll
    for (int mt = 0; mt < 2; ++mt) {
#pragma unroll
        for (int nt = 0; nt < 8; ++nt) {
            const int c  = n0 + wn*64 + nt*8 + t2;
            const float bv0 = bias[c], bv1 = bias[c+1];
            const int r0 = m0 + wm*32 + mt*16 + g;
            const int r1 = r0 + 8;
            float v00 = acc[mt][nt][0] + bv0, v01 = acc[mt][nt][1] + bv1;
            float v10 = acc[mt][nt][2] + bv0, v11 = acc[mt][nt][3] + bv1;
            if (permute) {
                const int h = c >> 6, d = c & 63;
                {
                    const int b = r0 >> 11, n = r0 & (SEQ - 1);
                    float* dst = out + ((size_t)(b*HEADS + h)*SEQ + n)*HD + d;
                    dst[0] = v00; dst[1] = v01;
                }
                {
                    const int b = r1 >> 11, n = r1 & (SEQ - 1);
                    float* dst = out + ((size_t)(b*HEADS + h)*SEQ + n)*HD + d;
                    dst[0] = v10; dst[1] = v11;
                }
            } else {
                float* d0 = out + (size_t)r0*DIM + c;
                float* d1 = out + (size_t)r1*DIM + c;
                d0[0] = v00; d0[1] = v01;
                d1[0] = v10; d1[1] = v11;
            }
        }
    }
}

// ============================================================
// HMMA flash attention. One (bh, 128-q tile) per CTA, 8 warps.
// Warp tile: queries wm*32..+31; keys wn*64..+63 (S) / full d (PV).
// S = Qhi*Khi + Qhi*Klo + Qlo*Khi  (fp32-grade).
// Softmax on register S; P refragmented (C-frag == A-frag identity),
// hi/lo split; PV with V transposed in smem (d-major rows).
// Cross-wn O partial sum via smem (aliased over dead V region).
// ============================================================
#define AS 72      /* ushort stride for Q/K rows (64 data + 8 pad) */
#define VS 136     /* ushort stride for Vt rows (128 data + 8 pad) */
#define SM_QH 0
#define SM_QL (128*AS)
#define SM_KH (2*128*AS)
#define SM_KL (3*128*AS)
#define SM_VH (4*128*AS)
#define SM_VL (SM_VH + 64*VS)
#define SM_USHORTS (SM_VL + 64*VS)           /* 54272 */
#define SMF_BYTES  (SM_USHORTS*2)            /* 108544 */
#define ATT2_SMEM_BYTES (SMF_BYTES + 896*4)  /* 112128 */

__global__ __launch_bounds__(256)
void attn_hmma()
{
    extern __shared__ unsigned short smu[];
    float* fm     = (float*)((char*)smu + SMF_BYTES);
    float* m_arr  = fm;            // [128]
    float* l_arr  = fm + 128;      // [128]
    float* sc_arr = fm + 256;      // [128]
    float* redm   = fm + 384;      // [2][128]
    float* reds   = fm + 640;      // [2][128]
    float* Osm    = (float*)((char*)smu + SM_VH*2);  // aliases V region; [128][68]

    const int tid  = threadIdx.x;
    const int wid  = tid >> 5, lane = tid & 31;
    const int wm   = wid & 3;
    const int wn   = wid >> 2;
    const int g    = lane >> 2;
    const int t2   = (lane & 3) * 2;
    const int lgrp = lane >> 3;
    const int lrow = lane & 7;

    const int bh = blockIdx.y;
    const int q0 = blockIdx.x * 128;
    const float* Qg = g_Q + (size_t)bh * SEQ * HD;
    const float* Kg = g_K + (size_t)bh * SEQ * HD;
    const float* Vg = g_V + (size_t)bh * SEQ * HD;

    const unsigned su = (unsigned)__cvta_generic_to_shared(smu);

    // ---- load Q tile once, hi/lo ----
#pragma unroll
    for (int it = 0; it < 8; ++it) {
        int idx = tid + it*256;
        int qr  = idx & 127;
        int d4  = (idx >> 7) * 4;
        float4 v = *(const float4*)(Qg + (size_t)(q0 + qr)*HD + d4);
        float x[4] = { v.x, v.y, v.z, v.w };
        int base = qr*AS + d4;
#pragma unroll
        for (int j = 0; j < 4; j += 2) {
            unsigned short h0 = f2bfu(x[j]),   h1 = f2bfu(x[j+1]);
            unsigned short l0 = f2bfu(x[j]   - bfu2f(h0));
            unsigned short l1 = f2bfu(x[j+1] - bfu2f(h1));
            *(unsigned*)&smu[SM_QH + base + j] = (unsigned)h0 | ((unsigned)h1 << 16);
            *(unsigned*)&smu[SM_QL + base + j] = (unsigned)l0 | ((unsigned)l1 << 16);
        }
    }
    if (tid < 128) { m_arr[tid] = -1e30f; l_arr[tid] = 0.0f; }

    float oacc[2][8][4];
#pragma unroll
    for (int mt = 0; mt < 2; ++mt)
#pragma unroll
        for (int nt = 0; nt < 8; ++nt)
#pragma unroll
            for (int r = 0; r < 4; ++r) oacc[mt][nt][r] = 0.0f;

    __syncthreads();

    const int row0b = wm*32 + g;          // + mt*16 (+8)

    for (int c0 = 0; c0 < SEQ; c0 += 128) {
        // ---- load K (row-major d) + V (transposed d-major), hi/lo ----
#pragma unroll
        for (int it = 0; it < 8; ++it) {
            int idx = tid + it*256;
            int kr  = idx & 127;
            int d4  = (idx >> 7) * 4;
            float4 kv = *(const float4*)(Kg + (size_t)(c0 + kr)*HD + d4);
            float xk[4] = { kv.x, kv.y, kv.z, kv.w };
            int base = kr*AS + d4;
#pragma unroll
            for (int j = 0; j < 4; j += 2) {
                unsigned short h0 = f2bfu(xk[j]),   h1 = f2bfu(xk[j+1]);
                unsigned short l0 = f2bfu(xk[j]   - bfu2f(h0));
                unsigned short l1 = f2bfu(xk[j+1] - bfu2f(h1));
                *(unsigned*)&smu[SM_KH + base + j] = (unsigned)h0 | ((unsigned)h1 << 16);
                *(unsigned*)&smu[SM_KL + base + j] = (unsigned)l0 | ((unsigned)l1 << 16);
            }
            float4 vv = *(const float4*)(Vg + (size_t)(c0 + kr)*HD + d4);
            float xv[4] = { vv.x, vv.y, vv.z, vv.w };
#pragma unroll
            for (int j = 0; j < 4; ++j) {
                unsigned short h = f2bfu(xv[j]);
                unsigned short l = f2bfu(xv[j] - bfu2f(h));
                smu[SM_VH + (d4+j)*VS + kr] = h;
                smu[SM_VL + (d4+j)*VS + kr] = l;
            }
        }
        __syncthreads();   // (1)

        // ---- S = Q K^T (split bf16) ----
        float sacc[2][8][4];
#pragma unroll
        for (int mt = 0; mt < 2; ++mt)
#pragma unroll
            for (int nt = 0; nt < 8; ++nt)
#pragma unroll
                for (int r = 0; r < 4; ++r) sacc[mt][nt][r] = 0.0f;

#pragma unroll
        for (int kc = 0; kc < 4; ++kc) {
            unsigned qH[2][4], qL[2][4];
#pragma unroll
            for (int mt = 0; mt < 2; ++mt) {
                unsigned qa = su + (unsigned)((SM_QH
                            + (wm*32 + mt*16 + (lgrp & 1)*8 + lrow)*AS
                            + kc*16 + (lgrp >> 1)*8) * 2);
                ldmatrix_x4(qH[mt], qa);
                ldmatrix_x4(qL[mt], qa + (unsigned)((SM_QL - SM_QH)*2));
            }
#pragma unroll
            for (int p = 0; p < 4; ++p) {
                unsigned kH[4], kL[4];
                unsigned ka = su + (unsigned)((SM_KH
                            + (wn*64 + p*16 + (lgrp >> 1)*8 + lrow)*AS
                            + kc*16 + (lgrp & 1)*8) * 2);
                ldmatrix_x4(kH, ka);
                ldmatrix_x4(kL, ka + (unsigned)((SM_KL - SM_KH)*2));
#pragma unroll
                for (int mt = 0; mt < 2; ++mt)
#pragma unroll
                    for (int o2 = 0; o2 < 2; ++o2) {
                        const int nt = p*2 + o2, o = o2*2;
                        mma16816(sacc[mt][nt], qH[mt], kH[o], kH[o+1]);
                        mma16816(sacc[mt][nt], qH[mt], kL[o], kL[o+1]);
                        mma16816(sacc[mt][nt], qL[mt], kH[o], kH[o+1]);
                    }
            }
        }

        // ---- row max (rows g, g+8 per mt), quad + cross-warp reduce ----
#pragma unroll
        for (int mt = 0; mt < 2; ++mt) {
            float mx0 = -1e30f, mx1 = -1e30f;
#pragma unroll
            for (int nt = 0; nt < 8; ++nt) {
                mx0 = fmaxf(mx0, fmaxf(sacc[mt][nt][0], sacc[mt][nt][1]));
                mx1 = fmaxf(mx1, fmaxf(sacc[mt][nt][2], sacc[mt][nt][3]));
            }
            mx0 = fmaxf(mx0, __shfl_xor_sync(0xffffffffu, mx0, 1));
            mx0 = fmaxf(mx0, __shfl_xor_sync(0xffffffffu, mx0, 2));
            mx1 = fmaxf(mx1, __shfl_xor_sync(0xffffffffu, mx1, 1));
            mx1 = fmaxf(mx1, __shfl_xor_sync(0xffffffffu, mx1, 2));
            if ((lane & 3) == 0) {
                redm[wn*128 + row0b + mt*16]     = mx0;
                redm[wn*128 + row0b + mt*16 + 8] = mx1;
            }
        }
        __syncthreads();   // (2)

        if (tid < 128) {
            float mx = fmaxf(redm[tid], redm[128 + tid]);
            float mo = m_arr[tid];
            float mn = fmaxf(mo, mx);
            m_arr[tid]  = mn;
            sc_arr[tid] = __expf(mo - mn);
        }
        __syncthreads();   // (3)

        // ---- O rescale ----
#pragma unroll
        for (int mt = 0; mt < 2; ++mt) {
            float s0 = sc_arr[row0b + mt*16];
            float s1 = sc_arr[row0b + mt*16 + 8];
#pragma unroll
            for (int nt = 0; nt < 8; ++nt) {
                oacc[mt][nt][0] *= s0; oacc[mt][nt][1] *= s0;
                oacc[mt][nt][2] *= s1; oacc[mt][nt][3] *= s1;
            }
        }

        // ---- exp, refragment P (hi/lo), PV per key-group ----
        float ps[2][2];
        ps[0][0] = ps[0][1] = ps[1][0] = ps[1][1] = 0.0f;
        float mn00 = m_arr[row0b], mn01 = m_arr[row0b + 8];
        float mn10 = m_arr[row0b + 16], mn11 = m_arr[row0b + 24];

#pragma unroll
        for (int kg = 0; kg < 4; ++kg) {
            unsigned pHf[2][4], pLf[2][4];
#pragma unroll
            for (int mt = 0; mt < 2; ++mt) {
                float mn0 = (mt == 0) ? mn00 : mn10;
                float mn1 = (mt == 0) ? mn01 : mn11;
#pragma unroll
                for (int o2 = 0; o2 < 2; ++o2) {
                    const int ntS = kg*2 + o2, sl = o2*2;
                    float e0 = __expf(sacc[mt][ntS][0] - mn0);
                    float e1 = __expf(sacc[mt][ntS][1] - mn0);
                    float e2 = __expf(sacc[mt][ntS][2] - mn1);
                    float e3 = __expf(sacc[mt][ntS][3] - mn1);
                    ps[mt][0] += e0 + e1;
                    ps[mt][1] += e2 + e3;
                    unsigned short h0 = f2bfu(e0), h1 = f2bfu(e1);
                    unsigned short h2 = f2bfu(e2), h3 = f2bfu(e3);
                    pHf[mt][sl]   = (unsigned)h0 | ((unsigned)h1 << 16);
                    pHf[mt][sl+1] = (unsigned)h2 | ((unsigned)h3 << 16);
                    unsigned short u0 = f2bfu(e0 - bfu2f(h0));
                    unsigned short u1 = f2bfu(e1 - bfu2f(h1));
                    unsigned short u2 = f2bfu(e2 - bfu2f(h2));
                    unsigned short u3 = f2bfu(e3 - bfu2f(h3));
                    pLf[mt][sl]   = (unsigned)u0 | ((unsigned)u1 << 16);
                    pLf[mt][sl+1] = (unsigned)u2 | ((unsigned)u3 << 16);
                }
            }
#pragma unroll
            for (int pd = 0; pd < 4; ++pd) {
                unsigned vH[4], vL[4];
                unsigned va = su + (unsigned)((SM_VH
                            + (pd*16 + (lgrp >> 1)*8 + lrow)*VS
                            + wn*64 + kg*16 + (lgrp & 1)*8) * 2);
                ldmatrix_x4(vH, va);
                ldmatrix_x4(vL, va + (unsigned)((SM_VL - SM_VH)*2));
#pragma unroll
                for (int mt = 0; mt < 2; ++mt)
#pragma unroll
                    for (int o2 = 0; o2 < 2; ++o2) {
                        const int nt = pd*2 + o2, o = o2*2;
                        mma16816(oacc[mt][nt], pHf[mt], vH[o], vH[o+1]);
                        mma16816(oacc[mt][nt], pHf[mt], vL[o], vL[o+1]);
                        mma16816(oacc[mt][nt], pLf[mt], vH[o], vH[o+1]);
                    }
            }
        }

        // ---- row sums -> l ----
#pragma unroll
        for (int mt = 0; mt < 2; ++mt) {
            float s0 = ps[mt][0], s1 = ps[mt][1];
            s0 += __shfl_xor_sync(0xffffffffu, s0, 1);
            s0 += __shfl_xor_sync(0xffffffffu, s0, 2);
            s1 += __shfl_xor_sync(0xffffffffu, s1, 1);
            s1 += __shfl_xor_sync(0xffffffffu, s1, 2);
            if ((lane & 3) == 0) {
                reds[wn*128 + row0b + mt*16]     = s0;
                reds[wn*128 + row0b + mt*16 + 8] = s1;
            }
        }
        __syncthreads();   // (4) — also: PV done reading V before next overwrite
        if (tid < 128)
            l_arr[tid] = l_arr[tid] * sc_arr[tid] + reds[tid] + reds[128 + tid];
        __syncthreads();   // (5)
    }

    // ---- cross-wn O reduction + write ----
    if (wn == 1) {
#pragma unroll
        for (int mt = 0; mt < 2; ++mt)
#pragma unroll
            for (int nt = 0; nt < 8; ++nt) {
                int r0 = row0b + mt*16, r1 = r0 + 8;
                int d  = nt*8 + t2;
                Osm[r0*68 + d]     = oacc[mt][nt][0];
                Osm[r0*68 + d + 1] = oacc[mt][nt][1];
                Osm[r1*68 + d]     = oacc[mt][nt][2];
                Osm[r1*68 + d + 1] = oacc[mt][nt][3];
            }
    }
    __syncthreads();
    if (wn == 0) {
        const int b = bh >> 4, h = bh & 15;
#pragma unroll
        for (int mt = 0; mt < 2; ++mt) {
            int r0 = row0b + mt*16, r1 = r0 + 8;
            float inv0 = ATT_SCALE / l_arr[r0];
            float inv1 = ATT_SCALE / l_arr[r1];
#pragma unroll
            for (int nt = 0; nt < 8; ++nt) {
                int d = nt*8 + t2;
                float v0 = (oacc[mt][nt][0] + Osm[r0*68 + d])     * inv0;
                float v1 = (oacc[mt][nt][1] + Osm[r0*68 + d + 1]) * inv0;
                float v2 = (oacc[mt][nt][2] + Osm[r1*68 + d])     * inv1;
                float v3 = (oacc[mt][nt][3] + Osm[r1*68 + d + 1]) * inv1;
                float* dst0 = g_C + ((size_t)(b*SEQ + q0 + r0)*HEADS + h)*HD + d;
                dst0[0] = v0; dst0[1] = v1;
                float* dst1 = g_C + ((size_t)(b*SEQ + q0 + r1)*HEADS + h)*HD + d;
                dst1[0] = v2; dst1[1] = v3;
            }
        }
    }
}

// ============================================================
extern "C" void kernel_launch(void* const* d_in, const int* in_sizes, int n_in,
                              void* d_out, int out_size)
{
    (void)in_sizes; (void)n_in; (void)out_size;
    const float* q  = (const float*)d_in[0];
    const float* k  = (const float*)d_in[1];
    const float* v  = (const float*)d_in[2];
    const float* Wq = (const float*)d_in[3];
    const float* bq = (const float*)d_in[4];
    const float* Wk = (const float*)d_in[5];
    const float* bk = (const float*)d_in[6];
    const float* Wv = (const float*)d_in[7];
    const float* bv = (const float*)d_in[8];
    const float* Wp = (const float*)d_in[9];
    const float* bp = (const float*)d_in[10];
    float* out = (float*)d_out;

    float *gq, *gk, *gv, *gc;
    cudaGetSymbolAddress((void**)&gq, g_Q);
    cudaGetSymbolAddress((void**)&gk, g_K);
    cudaGetSymbolAddress((void**)&gv, g_V);
    cudaGetSymbolAddress((void**)&gc, g_C);

    dim3 gb(DIM/128, MROWS/128);   // (8, 32)

    cudaFuncSetAttribute(gemm_hmma,
                         cudaFuncAttributeMaxDynamicSharedMemorySize,
                         GEMM_SMEM_BYTES);
    cudaFuncSetAttribute(attn_hmma,
                         cudaFuncAttributeMaxDynamicSharedMemorySize,
                         ATT2_SMEM_BYTES);

    gemm_hmma<<<gb, 256, GEMM_SMEM_BYTES>>>(q, Wq, bq, gq, 1);
    gemm_hmma<<<gb, 256, GEMM_SMEM_BYTES>>>(k, Wk, bk, gk, 1);
    gemm_hmma<<<gb, 256, GEMM_SMEM_BYTES>>>(v, Wv, bv, gv, 1);

    attn_hmma<<<dim3(SEQ/128, BATCH*HEADS), 256, ATT2_SMEM_BYTES>>>();

    gemm_hmma<<<gb, 256, GEMM_SMEM_BYTES>>>(gc, Wp, bp, out, 0);
}